// round 2
// baseline (speedup 1.0000x reference)
#include <cuda_runtime.h>

// LSTM2LINEAR: B=8192, T=1024, H=10, input_size=1.
// Thread layout: one thread per (batch, hidden-element r in 0..9).
// Per-thread registers hold the 4 gate rows of W_hh (40 floats), W_ih rows,
// fused biases, and (h_r, c_r). Hidden state h is exchanged through a
// double-buffered shared array with one __syncthreads per timestep.

#define T_STEPS 1024
#define HDIM 10
#define NB 16                      // batches per block
#define NTHREADS (NB * HDIM)       // 160

__device__ __forceinline__ float sigmoid_fast(float x) {
    // 1 / (1 + e^-x)  -> FMUL + MUFU.EX2 + FADD + MUFU.RCP
    return __fdividef(1.0f, 1.0f + __expf(-x));
}

__device__ __forceinline__ float tanh_fast(float x) {
    // 2 / (1 + e^-2x) - 1
    float r = __fdividef(2.0f, 1.0f + __expf(-2.0f * x));
    return r - 1.0f;
}

__global__ void __launch_bounds__(NTHREADS)
lstm2linear_kernel(const float* __restrict__ x,      // [B, T]
                   const float* __restrict__ W_ih,   // [4H, 1]
                   const float* __restrict__ W_hh,   // [4H, H]
                   const float* __restrict__ b_ih,   // [4H]
                   const float* __restrict__ b_hh,   // [4H]
                   const float* __restrict__ W_lin,  // [1, H]
                   const float* __restrict__ b_lin,  // [1]
                   float* __restrict__ out)          // [B]
{
    // h double buffer: rows padded to 12 floats (48B) for aligned float4 reads.
    __shared__ float hs[2][NB][12];

    const int tid = threadIdx.x;
    const int bl  = tid / HDIM;           // local batch 0..NB-1
    const int r   = tid % HDIM;           // hidden element 0..9
    const int b   = blockIdx.x * NB + bl; // global batch

    // --- load per-thread weights into registers ---
    float wI[HDIM], wF[HDIM], wG[HDIM], wO[HDIM];
#pragma unroll
    for (int j = 0; j < HDIM; j++) {
        wI[j] = W_hh[(0 * HDIM + r) * HDIM + j];
        wF[j] = W_hh[(1 * HDIM + r) * HDIM + j];
        wG[j] = W_hh[(2 * HDIM + r) * HDIM + j];
        wO[j] = W_hh[(3 * HDIM + r) * HDIM + j];
    }
    const float uI = W_ih[0 * HDIM + r];
    const float uF = W_ih[1 * HDIM + r];
    const float uG = W_ih[2 * HDIM + r];
    const float uO = W_ih[3 * HDIM + r];
    const float bI = b_ih[0 * HDIM + r] + b_hh[0 * HDIM + r];
    const float bF = b_ih[1 * HDIM + r] + b_hh[1 * HDIM + r];
    const float bG = b_ih[2 * HDIM + r] + b_hh[2 * HDIM + r];
    const float bO = b_ih[3 * HDIM + r] + b_hh[3 * HDIM + r];
    const float wlin = W_lin[r];

    float c = 0.0f;

    // init h buffer 0 to zero (including pad, harmless)
    hs[0][bl][r] = 0.0f;
    if (r < 2) hs[0][bl][HDIM + r] = 0.0f;
    __syncthreads();

    const float* xb = x + (size_t)b * T_STEPS;
    int p = 0;

    for (int t0 = 0; t0 < T_STEPS; t0 += 4) {
        // 4 timesteps of x at once (16B aligned: xb is 4KB aligned, t0 % 4 == 0)
        const float4 xv = *reinterpret_cast<const float4*>(xb + t0);
#pragma unroll
        for (int k = 0; k < 4; k++) {
            const float xt = (k == 0) ? xv.x : (k == 1) ? xv.y : (k == 2) ? xv.z : xv.w;

            // read full h vector for this batch (broadcast LDS within batch group)
            const float4 ha = *reinterpret_cast<const float4*>(&hs[p][bl][0]);
            const float4 hb = *reinterpret_cast<const float4*>(&hs[p][bl][4]);
            const float2 hc = *reinterpret_cast<const float2*>(&hs[p][bl][8]);
            const float hl[HDIM] = {ha.x, ha.y, ha.z, ha.w,
                                    hb.x, hb.y, hb.z, hb.w,
                                    hc.x, hc.y};

            float gi = fmaf(xt, uI, bI);
            float gf = fmaf(xt, uF, bF);
            float gg = fmaf(xt, uG, bG);
            float go = fmaf(xt, uO, bO);
#pragma unroll
            for (int j = 0; j < HDIM; j++) {
                gi = fmaf(wI[j], hl[j], gi);
                gf = fmaf(wF[j], hl[j], gf);
                gg = fmaf(wG[j], hl[j], gg);
                go = fmaf(wO[j], hl[j], go);
            }

            const float si = sigmoid_fast(gi);
            const float sf = sigmoid_fast(gf);
            const float tg = tanh_fast(gg);
            const float so = sigmoid_fast(go);

            c = fmaf(sf, c, si * tg);
            const float hn = so * tanh_fast(c);

            hs[p ^ 1][bl][r] = hn;
            __syncthreads();
            p ^= 1;
        }
    }

    // output = c_T @ W_lin^T + b_lin, reduced over the 10 elements per batch
    hs[0][bl][r] = c * wlin;
    __syncthreads();
    if (r == 0) {
        float s = b_lin[0];
#pragma unroll
        for (int j = 0; j < HDIM; j++) s += hs[0][bl][j];
        out[b] = s;
    }
}

extern "C" void kernel_launch(void* const* d_in, const int* in_sizes, int n_in,
                              void* d_out, int out_size) {
    const float* x     = (const float*)d_in[0];  // [B, T, 1]
    const float* W_ih  = (const float*)d_in[1];  // [4H, 1]
    const float* W_hh  = (const float*)d_in[2];  // [4H, H]
    const float* b_ih  = (const float*)d_in[3];  // [4H]
    const float* b_hh  = (const float*)d_in[4];  // [4H]
    const float* W_lin = (const float*)d_in[5];  // [1, H]
    const float* b_lin = (const float*)d_in[6];  // [1]
    float* out = (float*)d_out;                  // [B, 1]

    const int B = in_sizes[0] / T_STEPS;         // 8192
    const int blocks = B / NB;                   // 512

    lstm2linear_kernel<<<blocks, NTHREADS>>>(x, W_ih, W_hh, b_ih, b_hh,
                                             W_lin, b_lin, out);
}